// round 11
// baseline (speedup 1.0000x reference)
#include <cuda_runtime.h>

#define B_  65536
#define T_  28
#define IN_ 28
#define HD_ 28
#define NC_ 10

typedef unsigned long long ull;

__device__ __forceinline__ ull pack2(float lo, float hi) {
    ull r; asm("mov.b64 %0, {%1, %2};" : "=l"(r) : "f"(lo), "f"(hi)); return r;
}
__device__ __forceinline__ void fma2(ull& acc, ull a, ull b) {
    asm("fma.rn.f32x2 %0, %1, %2, %0;" : "+l"(acc) : "l"(a), "l"(b));
}
__device__ __forceinline__ float hadd2(ull v) {
    float lo, hi; asm("mov.b64 {%0, %1}, %2;" : "=f"(lo), "=f"(hi) : "l"(v));
    return lo + hi;
}
__device__ __forceinline__ float tanh_a(float v) {
    float r; asm("tanh.approx.f32 %0, %1;" : "=f"(r) : "f"(v)); return r;
}
__device__ __forceinline__ float sigm(float v) {
    return fmaf(0.5f, tanh_a(0.5f * v), 0.5f);
}

// One LSTM unit, one sample. Gate rows at row, row+nr, row+2nr, row+3nr;
// each row = [W_k(28) | W_he(4)] (32 floats, 128B). k: 14 pairs; he: 2 pairs.
__device__ __forceinline__ float lstm_unit(
    const float* __restrict__ sW, int row, int nr,
    const float* __restrict__ sB, int unit,
    const ull* __restrict__ k, ull heA, ull heB, float& c)
{
    float4 bb = *(const float4*)&sB[unit * 4];   // bi, bf, bg, bo
    ull aI = pack2(bb.x, 0.f);
    ull aF = pack2(bb.y, 0.f);
    ull aG = pack2(bb.z, 0.f);
    ull aO = pack2(bb.w, 0.f);
    const float* wi = sW + (size_t)row * 32;
    const float* wf = wi + (size_t)nr * 32;
    const float* wg = wf + (size_t)nr * 32;
    const float* wo = wg + (size_t)nr * 32;
#pragma unroll
    for (int q = 0; q < 7; ++q) {
        ulonglong2 Wi = *(const ulonglong2*)&wi[q * 4];
        ulonglong2 Wf = *(const ulonglong2*)&wf[q * 4];
        ulonglong2 Wg = *(const ulonglong2*)&wg[q * 4];
        ulonglong2 Wo = *(const ulonglong2*)&wo[q * 4];
        ull kA = k[2 * q], kB = k[2 * q + 1];
        fma2(aI, Wi.x, kA); fma2(aI, Wi.y, kB);
        fma2(aF, Wf.x, kA); fma2(aF, Wf.y, kB);
        fma2(aG, Wg.x, kA); fma2(aG, Wg.y, kB);
        fma2(aO, Wo.x, kA); fma2(aO, Wo.y, kB);
    }
    {   // columns 28..31: he pairs
        ulonglong2 Wi = *(const ulonglong2*)&wi[28];
        ulonglong2 Wf = *(const ulonglong2*)&wf[28];
        ulonglong2 Wg = *(const ulonglong2*)&wg[28];
        ulonglong2 Wo = *(const ulonglong2*)&wo[28];
        fma2(aI, Wi.x, heA); fma2(aI, Wi.y, heB);
        fma2(aF, Wf.x, heA); fma2(aF, Wf.y, heB);
        fma2(aG, Wg.x, heA); fma2(aG, Wg.y, heB);
        fma2(aO, Wo.x, heA); fma2(aO, Wo.y, heB);
    }
    float gi = sigm(hadd2(aI)), gf = sigm(hadd2(aF));
    float gg = tanh_a(hadd2(aG)), go = sigm(hadd2(aO));
    float cn = gf * c + gi * gg;
    c = cn;
    return go * tanh_a(cn);
}

// block = 128 thr; each THREAD owns one sample. 128 samples/CTA, 512 CTAs.
__global__ void __launch_bounds__(128, 3)
ae_lstm_kernel(const float* __restrict__ x,
               const float* __restrict__ eWih, const float* __restrict__ eWhh,
               const float* __restrict__ eb,
               const float* __restrict__ dWih, const float* __restrict__ dWhh,
               const float* __restrict__ db,
               const float* __restrict__ uW,  const float* __restrict__ ubv,
               float* __restrict__ out, float* __restrict__ pred)
{
    __shared__ __align__(16) float sWd[112 * 32];   // [Whh(28)|Wih(4)] per gate row
    __shared__ __align__(16) float sWe[16 * 32];    // [Wih(28)|Whh(4)]
    __shared__ __align__(16) float sBd[28 * 4];     // (bi,bf,bg,bo) per unit
    __shared__ __align__(16) float sBe[4 * 4];
    __shared__ __align__(16) float sU[NC_ * 30];    // [U(28)|ub|pad]

    const int tid = threadIdx.x;
    for (int i = tid; i < 112 * 32; i += 128) {
        int row = i >> 5, c = i & 31;
        sWd[i] = (c < 28) ? dWhh[row * 28 + c] : dWih[row * 4 + (c - 28)];
    }
    for (int i = tid; i < 16 * 32; i += 128) {
        int row = i >> 5, c = i & 31;
        sWe[i] = (c < 28) ? eWih[row * 28 + c] : eWhh[row * 4 + (c - 28)];
    }
    if (tid < 112) {
        int unit = tid >> 2, g = tid & 3;
        sBd[tid] = db[g * 28 + unit];
    }
    if (tid < 16) {
        int unit = tid >> 2, g = tid & 3;
        sBe[tid] = eb[g * 4 + unit];
    }
    for (int i = tid; i < NC_ * 30; i += 128) {
        int k = i / 30, c = i % 30;
        sU[i] = (c < 28) ? uW[k * 28 + c] : ((c == 28) ? ubv[k] : 0.f);
    }
    __syncthreads();

    const int s = blockIdx.x * 128 + tid;
    const float* xg = x   + (size_t)s * (T_ * IN_);
    float*       og = out + (size_t)s * (T_ * HD_);

    // ---------- lane-local state ----------
    ull   hd[14];
    float cd[28];
    ull   he[2] = {0ull, 0ull};
    float ce[4] = {0.f, 0.f, 0.f, 0.f};
#pragma unroll
    for (int q = 0; q < 14; ++q) hd[q] = 0ull;
#pragma unroll
    for (int j = 0; j < 28; ++j) cd[j] = 0.f;

    // x(0) into registers
    ull xp[14];
#pragma unroll
    for (int q = 0; q < 7; ++q) {
        ulonglong2 v = __ldg((const ulonglong2*)xg + q);
        xp[2 * q] = v.x; xp[2 * q + 1] = v.y;
    }

#pragma unroll 1
    for (int t = 0; t < T_; ++t) {
        // ===== encoder(t): 4 units, k = [x(t) | he] =====
        float hen[4];
#pragma unroll
        for (int e = 0; e < 4; ++e)
            hen[e] = lstm_unit(sWe, e, 4, sBe, e, xp, he[0], he[1], ce[e]);
        he[0] = pack2(hen[0], hen[1]);
        he[1] = pack2(hen[2], hen[3]);

        // ===== prefetch x(t+1) into xp (dead now; hidden under decoder) =====
        if (t + 1 < T_) {
#pragma unroll
            for (int q = 0; q < 7; ++q) {
                ulonglong2 v = __ldg((const ulonglong2*)(xg + (t + 1) * IN_) + q);
                xp[2 * q] = v.x; xp[2 * q + 1] = v.y;
            }
        }

        // ===== decoder(t): 28 units, k = [hd(t-1) | he(t)] =====
        ull   hn[14];
        float hp;
#pragma unroll
        for (int j = 0; j < 28; ++j) {
            float h = lstm_unit(sWd, j, 28, sBd, j, hd, he[0], he[1], cd[j]);
            if (j & 1) {
                ull p = pack2(hp, h);
                hn[j >> 1] = p;
                *(ull*)(og + t * HD_ + (j - 1)) = p;
            } else hp = h;
        }
#pragma unroll
        for (int q = 0; q < 14; ++q) hd[q] = hn[q];
    }

    // ===== classifier + softmax (lane-local) =====
    {
        float lg[NC_];
        float mx = -3.4e38f;
#pragma unroll
        for (int k = 0; k < NC_; ++k) {
            ull a = pack2(sU[k * 30 + 28], 0.f);
#pragma unroll
            for (int m = 0; m < 14; ++m)
                fma2(a, *(const ull*)&sU[k * 30 + 2 * m], hd[m]);
            lg[k] = hadd2(a);
            mx = fmaxf(mx, lg[k]);
        }
        float sum = 0.f;
#pragma unroll
        for (int k = 0; k < NC_; ++k) { float e = __expf(lg[k] - mx); lg[k] = e; sum += e; }
        float inv = __fdividef(1.0f, sum);
        float2* pp = (float2*)(pred + (size_t)s * NC_);
#pragma unroll
        for (int k = 0; k < 5; ++k)
            pp[k] = make_float2(lg[2 * k] * inv, lg[2 * k + 1] * inv);
    }
}

extern "C" void kernel_launch(void* const* d_in, const int* in_sizes, int n_in,
                              void* d_out, int out_size)
{
    const float* x    = (const float*)d_in[0];
    const float* eWih = (const float*)d_in[1];
    const float* eWhh = (const float*)d_in[2];
    const float* eb   = (const float*)d_in[3];
    const float* dWih = (const float*)d_in[4];
    const float* dWhh = (const float*)d_in[5];
    const float* db   = (const float*)d_in[6];
    const float* uW   = (const float*)d_in[7];
    const float* ub   = (const float*)d_in[8];

    float* out  = (float*)d_out;                 // [B, T, 28]
    float* pred = out + (size_t)B_ * T_ * HD_;   // [1, B, 10]

    dim3 grid(B_ / 128), block(128);             // 1 sample per thread
    ae_lstm_kernel<<<grid, block>>>(x, eWih, eWhh, eb, dWih, dWhh, db, uW, ub,
                                    out, pred);
}

// round 12
// speedup vs baseline: 1.4099x; 1.4099x over previous
#include <cuda_runtime.h>

#define B_  65536
#define T_  28
#define IN_ 28
#define HD_ 28
#define NC_ 10
#define NS  3          // samples per warp

typedef unsigned long long ull;

__device__ __forceinline__ ull pack2(float lo, float hi) {
    ull r; asm("mov.b64 %0, {%1, %2};" : "=l"(r) : "f"(lo), "f"(hi)); return r;
}
__device__ __forceinline__ void fma2(ull& acc, ull a, ull b) {
    asm("fma.rn.f32x2 %0, %1, %2, %0;" : "+l"(acc) : "l"(a), "l"(b));
}
__device__ __forceinline__ float hadd2(ull v) {
    float lo, hi; asm("mov.b64 {%0, %1}, %2;" : "=f"(lo), "=f"(hi) : "l"(v));
    return lo + hi;
}
__device__ __forceinline__ float tanh_a(float v) {
    float r; asm("tanh.approx.f32 %0, %1;" : "=f"(r) : "f"(v)); return r;
}
// sigmoid of (2x) given pre-scaled input x = 0.5*logit  (0.5 folded into weights)
__device__ __forceinline__ float sigm_pre(float v) {
    return fmaf(0.5f, tanh_a(v), 0.5f);
}

// encoder step: half-warp-split dot, gate-parallel. Weights pre-scaled (0.5 for
// sigmoid rows). he(t-1) passed in as packed pairs; he(t) written to hebw by lanes 0-3.
__device__ __forceinline__ void enc_step(const ull (&ew)[8], ull ebp, int xoff,
                                         float eA, float eC, int u, int lane,
                                         const float* xrow, ull hp0, ull hp1,
                                         float& ce, float* hebw_s)
{
    const ulonglong2* xp = (const ulonglong2*)xrow + xoff;
    ulonglong2 v0 = xp[0], v1 = xp[1], v2 = xp[2], v3 = xp[3];
    ull o6 = xoff ? hp0 : v3.x;
    ull o7 = xoff ? hp1 : v3.y;
    ull acc0 = ebp;
    ull acc1 = 0ull;
    fma2(acc0, ew[0], v0.x); fma2(acc1, ew[1], v0.y);
    fma2(acc0, ew[2], v1.x); fma2(acc1, ew[3], v1.y);
    fma2(acc0, ew[4], v2.x); fma2(acc1, ew[5], v2.y);
    fma2(acc0, ew[6], o6);   fma2(acc1, ew[7], o7);
    float s = hadd2(acc0) + hadd2(acc1);
    s += __shfl_xor_sync(0xffffffffu, s, 16, 32);
    float gact = fmaf(eA, tanh_a(s), eC);      // sigm_pre or tanh per row
    float ai = __shfl_sync(0xffffffffu, gact, u,      32);
    float af = __shfl_sync(0xffffffffu, gact, u + 4,  32);
    float ag = __shfl_sync(0xffffffffu, gact, u + 8,  32);
    float ao = __shfl_sync(0xffffffffu, gact, u + 12, 32);
    float cen = af * ce + ai * ag;             // each lane tracks unit u = lane&3
    ce = cen;
    float hn = ao * tanh_a(cen);
    if (lane < 4) hebw_s[lane] = hn;           // owner lanes publish he(t)
}

// block = 128 threads = 4 warps = 12 samples (3 per warp, interleaved ILP)
__global__ void __launch_bounds__(128, 2)
ae_lstm_kernel(const float* __restrict__ x,
               const float* __restrict__ eWih, const float* __restrict__ eWhh,
               const float* __restrict__ eb,
               const float* __restrict__ dWih, const float* __restrict__ dWhh,
               const float* __restrict__ db,
               const float* __restrict__ uW,  const float* __restrict__ ubv,
               float* __restrict__ out, float* __restrict__ pred)
{
    __shared__ float sU[NC_ * HD_ + NC_];
    __shared__ __align__(16) float hbuf[4][NS][2][32];
    __shared__ __align__(16) float xbuf[4][NS][2][32];
    __shared__ __align__(16) float hebuf[4][NS * 4 + 4];   // he(t) per warp/sample

    for (int i = threadIdx.x; i < NC_ * HD_; i += blockDim.x) sU[i] = uW[i];
    for (int i = threadIdx.x; i < NC_;       i += blockDim.x) sU[NC_ * HD_ + i] = ubv[i];
    __syncthreads();

    const int lane = threadIdx.x & 31;
    const int w    = threadIdx.x >> 5;
    const int base = blockIdx.x * (4 * NS) + w * NS;

    int  bs[NS];
    bool vs[NS];
#pragma unroll
    for (int s = 0; s < NS; ++s) {
        int bb = base + s;
        vs[s] = (bb < B_);
        bs[s] = vs[s] ? bb : (B_ - 1);
    }

    // ---------- decoder weights -> registers; i/f/o rows pre-scaled by 0.5 ----------
    const int j = (lane < HD_) ? lane : (HD_ - 1);
    ull   dwhh[4][14];
    ull   dwih[4][2];
    ull   dbp[4];
#pragma unroll
    for (int g = 0; g < 4; ++g) {
        const float sc = (g == 2) ? 1.0f : 0.5f;
        const float4* r4 = (const float4*)(dWhh + (size_t)(g * HD_ + j) * HD_);
#pragma unroll
        for (int q = 0; q < 7; ++q) {
            float4 v = __ldg(r4 + q);
            dwhh[g][2 * q]     = pack2(sc * v.x, sc * v.y);
            dwhh[g][2 * q + 1] = pack2(sc * v.z, sc * v.w);
        }
        float4 u4 = __ldg((const float4*)(dWih + (g * HD_ + j) * 4));
        dwih[g][0] = pack2(sc * u4.x, sc * u4.y);
        dwih[g][1] = pack2(sc * u4.z, sc * u4.w);
        dbp[g] = pack2(sc * __ldg(db + g * HD_ + j), 0.f);
    }

    // ---------- encoder weights (half-warp split); sigmoid rows pre-scaled ----------
    const int r = lane & 15;
    const int u = lane & 3;
    const int xoff = (lane < 16) ? 0 : 4;
    const bool  eg = (r >= 8 && r < 12);        // g-gate rows
    const float es = eg ? 1.0f : 0.5f;
    const float eA = eg ? 1.0f : 0.5f;
    const float eC = eg ? 0.0f : 0.5f;
    ull ew[8];
    ull ebp;
    {
        const float2* p = (const float2*)(eWih + (size_t)r * IN_);
        if (lane < 16) {
#pragma unroll
            for (int m = 0; m < 8; ++m) { float2 v = __ldg(p + m); ew[m] = pack2(es * v.x, es * v.y); }
            ebp = pack2(es * __ldg(eb + r), 0.f);
        } else {
#pragma unroll
            for (int m = 0; m < 6; ++m) { float2 v = __ldg(p + 8 + m); ew[m] = pack2(es * v.x, es * v.y); }
            const float2* ph = (const float2*)(eWhh + r * 4);
            float2 h0 = __ldg(ph), h1 = __ldg(ph + 1);
            ew[6] = pack2(es * h0.x, es * h0.y);
            ew[7] = pack2(es * h1.x, es * h1.y);
            ebp = 0ull;
        }
    }

    // ---------- state ----------
    float cd[NS], ce[NS];
    const float* xr[NS];
#pragma unroll
    for (int s = 0; s < NS; ++s) {
        cd[s] = 0.f; ce[s] = 0.f;
        xr[s] = x + (size_t)bs[s] * T_ * IN_;
    }

    // ---------- prologue: stage x0,x1; zero hd(-1); enc(0) ----------
    if (lane < IN_) {
#pragma unroll
        for (int s = 0; s < NS; ++s) {
            xbuf[w][s][0][lane] = __ldg(xr[s] + lane);
            xbuf[w][s][1][lane] = __ldg(xr[s] + IN_ + lane);
            hbuf[w][s][1][lane] = 0.f;
        }
    }
    __syncwarp();
#pragma unroll
    for (int s = 0; s < NS; ++s)
        enc_step(ew, ebp, xoff, eA, eC, u, lane, xbuf[w][s][0], 0ull, 0ull,
                 ce[s], &hebuf[w][s * 4]);
    __syncwarp();

    // ---------- unified loop: t in [1, T_]; body = dec(t-1) || enc(t) ----------
#pragma unroll 1
    for (int t = 1; t <= T_; ++t) {
        // he(t-1) via one broadcast LDS.128 per sample
        ull hp0[NS], hp1[NS];
#pragma unroll
        for (int s = 0; s < NS; ++s) {
            ulonglong2 hv = *(const ulonglong2*)&hebuf[w][s * 4];
            hp0[s] = hv.x; hp1[s] = hv.y;
        }

        float xn[NS];
#pragma unroll
        for (int s = 0; s < NS; ++s) xn[s] = 0.f;
        if (t + 1 < T_ && lane < IN_) {
#pragma unroll
            for (int s = 0; s < NS; ++s) xn[s] = __ldg(xr[s] + (t + 1) * IN_ + lane);
        }

        // ---- tri-sample decoder pre-activations (shared weight regs) ----
        ull a[NS][4];
#pragma unroll
        for (int s = 0; s < NS; ++s) {
#pragma unroll
            for (int g = 0; g < 4; ++g) a[s][g] = dbp[g];
            fma2(a[s][0], dwih[0][0], hp0[s]); fma2(a[s][0], dwih[0][1], hp1[s]);
            fma2(a[s][1], dwih[1][0], hp0[s]); fma2(a[s][1], dwih[1][1], hp1[s]);
            fma2(a[s][2], dwih[2][0], hp0[s]); fma2(a[s][2], dwih[2][1], hp1[s]);
            fma2(a[s][3], dwih[3][0], hp0[s]); fma2(a[s][3], dwih[3][1], hp1[s]);
        }
        const int ph = t & 1;
#pragma unroll
        for (int m = 0; m < 7; ++m) {
#pragma unroll
            for (int s = 0; s < NS; ++s) {
                ulonglong2 v = ((const ulonglong2*)hbuf[w][s][ph])[m];
                fma2(a[s][0], dwhh[0][2*m], v.x); fma2(a[s][0], dwhh[0][2*m+1], v.y);
                fma2(a[s][1], dwhh[1][2*m], v.x); fma2(a[s][1], dwhh[1][2*m+1], v.y);
                fma2(a[s][2], dwhh[2][2*m], v.x); fma2(a[s][2], dwhh[2][2*m+1], v.y);
                fma2(a[s][3], dwhh[3][2*m], v.x); fma2(a[s][3], dwhh[3][2*m+1], v.y);
            }
        }

        // ---- encoders (skip on final iteration); consume he(t-1), publish he(t) ----
        if (t < T_) {
#pragma unroll
            for (int s = 0; s < NS; ++s)
                enc_step(ew, ebp, xoff, eA, eC, u, lane, xbuf[w][s][ph],
                         hp0[s], hp1[s], ce[s], &hebuf[w][s * 4]);
        }

        // ---- activations + stores ----
#pragma unroll
        for (int s = 0; s < NS; ++s) {
            float gi = sigm_pre(hadd2(a[s][0]));
            float gf = sigm_pre(hadd2(a[s][1]));
            float gg = tanh_a(hadd2(a[s][2]));
            float go = sigm_pre(hadd2(a[s][3]));
            float c  = gf * cd[s] + gi * gg;
            cd[s] = c;
            float h  = go * tanh_a(c);
            if (lane < HD_) {
                if (vs[s]) out[(size_t)bs[s] * T_ * HD_ + (t - 1) * HD_ + lane] = h;
                hbuf[w][s][(t - 1) & 1][lane] = h;
                if (t + 1 < T_) xbuf[w][s][(t + 1) & 1][lane] = xn[s];
            }
        }
        __syncwarp();
    }

    // ---------- classifier head + softmax per sample ----------
#pragma unroll
    for (int s = 0; s < NS; ++s) {
        ull hd[14];
        const ulonglong2* hv = (const ulonglong2*)hbuf[w][s][1];
#pragma unroll
        for (int m = 0; m < 7; ++m) { ulonglong2 v = hv[m]; hd[2*m] = v.x; hd[2*m+1] = v.y; }

        const int k = (lane < NC_) ? lane : (NC_ - 1);
        const ull* uwk = (const ull*)(sU + k * HD_);
        ull acc = pack2(sU[NC_ * HD_ + k], 0.f);
#pragma unroll
        for (int m = 0; m < 14; ++m) fma2(acc, uwk[m], hd[m]);
        float lg = hadd2(acc);

        float lv = (lane < NC_) ? lg : -3.4e38f;
#pragma unroll
        for (int o2 = 8; o2 >= 1; o2 >>= 1)
            lv = fmaxf(lv, __shfl_xor_sync(0xffffffffu, lv, o2, 16));
        float e = (lane < NC_) ? __expf(lg - lv) : 0.f;
        float sum = e;
#pragma unroll
        for (int o2 = 8; o2 >= 1; o2 >>= 1)
            sum += __shfl_xor_sync(0xffffffffu, sum, o2, 16);
        if (lane < NC_ && vs[s])
            pred[(size_t)bs[s] * NC_ + lane] = e * __fdividef(1.0f, sum);
    }
}

extern "C" void kernel_launch(void* const* d_in, const int* in_sizes, int n_in,
                              void* d_out, int out_size)
{
    const float* x    = (const float*)d_in[0];
    const float* eWih = (const float*)d_in[1];
    const float* eWhh = (const float*)d_in[2];
    const float* eb   = (const float*)d_in[3];
    const float* dWih = (const float*)d_in[4];
    const float* dWhh = (const float*)d_in[5];
    const float* db   = (const float*)d_in[6];
    const float* uW   = (const float*)d_in[7];
    const float* ub   = (const float*)d_in[8];

    float* out  = (float*)d_out;                 // [B, T, 28]
    float* pred = out + (size_t)B_ * T_ * HD_;   // [1, B, 10]

    const int spb = 4 * NS;                      // samples per block
    dim3 grid((B_ + spb - 1) / spb), block(128);
    ae_lstm_kernel<<<grid, block>>>(x, eWih, eWhh, eb, dWih, dWhh, db, uW, ub,
                                    out, pred);
}

// round 13
// speedup vs baseline: 1.4925x; 1.0586x over previous
#include <cuda_runtime.h>

#define B_  65536
#define T_  28
#define IN_ 28
#define HD_ 28
#define NC_ 10
#define NS  3          // samples per warp

typedef unsigned long long ull;

__device__ __forceinline__ ull pack2(float lo, float hi) {
    ull r; asm("mov.b64 %0, {%1, %2};" : "=l"(r) : "f"(lo), "f"(hi)); return r;
}
__device__ __forceinline__ void fma2(ull& acc, ull a, ull b) {
    asm("fma.rn.f32x2 %0, %1, %2, %0;" : "+l"(acc) : "l"(a), "l"(b));
}
__device__ __forceinline__ float hadd2(ull v) {
    float lo, hi; asm("mov.b64 {%0, %1}, %2;" : "=f"(lo), "=f"(hi) : "l"(v));
    return lo + hi;
}
__device__ __forceinline__ float tanh_a(float v) {
    float r; asm("tanh.approx.f32 %0, %1;" : "=f"(r) : "f"(v)); return r;
}
// sigmoid(2x) given pre-scaled input x = 0.5*logit (0.5 folded into weights)
__device__ __forceinline__ float sigm_pre(float v) {
    return fmaf(0.5f, tanh_a(v), 0.5f);
}

// encoder step: half-warp-split dot, gate-parallel, shuffle-based he handoff (R7).
// Weights pre-scaled (0.5 on sigmoid rows); no eB multiply needed.
__device__ __forceinline__ void enc_step(const ull (&ew)[8], ull ebp, int xoff,
                                         float eA, float eC, int u,
                                         const float* xrow,
                                         ull& he01, ull& he23, float& ce)
{
    const ulonglong2* xp = (const ulonglong2*)xrow + xoff;
    ulonglong2 v0 = xp[0], v1 = xp[1], v2 = xp[2], v3 = xp[3];
    ull o6 = xoff ? he01 : v3.x;
    ull o7 = xoff ? he23 : v3.y;
    ull acc0 = ebp;
    ull acc1 = 0ull;
    fma2(acc0, ew[0], v0.x); fma2(acc1, ew[1], v0.y);
    fma2(acc0, ew[2], v1.x); fma2(acc1, ew[3], v1.y);
    fma2(acc0, ew[4], v2.x); fma2(acc1, ew[5], v2.y);
    fma2(acc0, ew[6], o6);   fma2(acc1, ew[7], o7);
    float s = hadd2(acc0) + hadd2(acc1);
    s += __shfl_xor_sync(0xffffffffu, s, 16, 32);
    float gact = fmaf(eA, tanh_a(s), eC);      // sigm_pre or tanh per row
    float ai = __shfl_sync(0xffffffffu, gact, u,      32);
    float af = __shfl_sync(0xffffffffu, gact, u + 4,  32);
    float ag = __shfl_sync(0xffffffffu, gact, u + 8,  32);
    float ao = __shfl_sync(0xffffffffu, gact, u + 12, 32);
    float cen = af * ce + ai * ag;             // each lane tracks unit u = lane&3
    ce = cen;
    float hn = ao * tanh_a(cen);
    he01 = pack2(__shfl_sync(0xffffffffu, hn, 0, 32),
                 __shfl_sync(0xffffffffu, hn, 1, 32));
    he23 = pack2(__shfl_sync(0xffffffffu, hn, 2, 32),
                 __shfl_sync(0xffffffffu, hn, 3, 32));
}

// block = 128 threads = 4 warps = 12 samples (3 per warp, interleaved ILP)
__global__ void __launch_bounds__(128, 2)
ae_lstm_kernel(const float* __restrict__ x,
               const float* __restrict__ eWih, const float* __restrict__ eWhh,
               const float* __restrict__ eb,
               const float* __restrict__ dWih, const float* __restrict__ dWhh,
               const float* __restrict__ db,
               const float* __restrict__ uW,  const float* __restrict__ ubv,
               float* __restrict__ out, float* __restrict__ pred)
{
    __shared__ float sU[NC_ * HD_ + NC_];
    __shared__ __align__(16) float hbuf[4][NS][2][32];
    __shared__ __align__(16) float xbuf[4][NS][2][32];

    for (int i = threadIdx.x; i < NC_ * HD_; i += blockDim.x) sU[i] = uW[i];
    for (int i = threadIdx.x; i < NC_;       i += blockDim.x) sU[NC_ * HD_ + i] = ubv[i];
    __syncthreads();

    const int lane = threadIdx.x & 31;
    const int w    = threadIdx.x >> 5;
    const int base = blockIdx.x * (4 * NS) + w * NS;

    int  bs[NS];
    bool vs[NS];
#pragma unroll
    for (int s = 0; s < NS; ++s) {
        int bb = base + s;
        vs[s] = (bb < B_);
        bs[s] = vs[s] ? bb : (B_ - 1);
    }

    // ---------- decoder weights -> registers; i/f/o rows pre-scaled by 0.5 ----------
    const int j = (lane < HD_) ? lane : (HD_ - 1);
    ull dwhh[4][14];
    ull dwih[4][2];
    ull dbp[4];
#pragma unroll
    for (int g = 0; g < 4; ++g) {
        const float sc = (g == 2) ? 1.0f : 0.5f;
        const float4* r4 = (const float4*)(dWhh + (size_t)(g * HD_ + j) * HD_);
#pragma unroll
        for (int q = 0; q < 7; ++q) {
            float4 v = __ldg(r4 + q);
            dwhh[g][2 * q]     = pack2(sc * v.x, sc * v.y);
            dwhh[g][2 * q + 1] = pack2(sc * v.z, sc * v.w);
        }
        float4 u4 = __ldg((const float4*)(dWih + (g * HD_ + j) * 4));
        dwih[g][0] = pack2(sc * u4.x, sc * u4.y);
        dwih[g][1] = pack2(sc * u4.z, sc * u4.w);
        dbp[g] = pack2(sc * __ldg(db + g * HD_ + j), 0.f);
    }

    // ---------- encoder weights (half-warp split); sigmoid rows pre-scaled ----------
    const int r = lane & 15;
    const int u = lane & 3;
    const int xoff = (lane < 16) ? 0 : 4;
    const bool  eg = (r >= 8 && r < 12);        // g-gate rows
    const float es = eg ? 1.0f : 0.5f;
    const float eA = eg ? 1.0f : 0.5f;
    const float eC = eg ? 0.0f : 0.5f;
    ull ew[8];
    ull ebp;
    {
        const float2* p = (const float2*)(eWih + (size_t)r * IN_);
        if (lane < 16) {
#pragma unroll
            for (int m = 0; m < 8; ++m) { float2 v = __ldg(p + m); ew[m] = pack2(es * v.x, es * v.y); }
            ebp = pack2(es * __ldg(eb + r), 0.f);
        } else {
#pragma unroll
            for (int m = 0; m < 6; ++m) { float2 v = __ldg(p + 8 + m); ew[m] = pack2(es * v.x, es * v.y); }
            const float2* ph = (const float2*)(eWhh + r * 4);
            float2 h0 = __ldg(ph), h1 = __ldg(ph + 1);
            ew[6] = pack2(es * h0.x, es * h0.y);
            ew[7] = pack2(es * h1.x, es * h1.y);
            ebp = 0ull;
        }
    }

    // ---------- state ----------
    ull   he01[NS], he23[NS];
    float cd[NS], ce[NS];
    const float* xr[NS];
#pragma unroll
    for (int s = 0; s < NS; ++s) {
        he01[s] = 0ull; he23[s] = 0ull; cd[s] = 0.f; ce[s] = 0.f;
        xr[s] = x + (size_t)bs[s] * T_ * IN_;
    }

    // ---------- prologue: stage x0,x1; zero hd(-1); enc(0) ----------
    if (lane < IN_) {
#pragma unroll
        for (int s = 0; s < NS; ++s) {
            xbuf[w][s][0][lane] = __ldg(xr[s] + lane);
            xbuf[w][s][1][lane] = __ldg(xr[s] + IN_ + lane);
            hbuf[w][s][1][lane] = 0.f;
        }
    }
    __syncwarp();
#pragma unroll
    for (int s = 0; s < NS; ++s)
        enc_step(ew, ebp, xoff, eA, eC, u, xbuf[w][s][0], he01[s], he23[s], ce[s]);

    // ---------- unified loop: t in [1, T_]; body = dec(t-1) || enc(t) ----------
#pragma unroll 1
    for (int t = 1; t <= T_; ++t) {
        ull hp0[NS], hp1[NS];
#pragma unroll
        for (int s = 0; s < NS; ++s) { hp0[s] = he01[s]; hp1[s] = he23[s]; }

        float xn[NS];
#pragma unroll
        for (int s = 0; s < NS; ++s) xn[s] = 0.f;
        if (t + 1 < T_ && lane < IN_) {
#pragma unroll
            for (int s = 0; s < NS; ++s) xn[s] = __ldg(xr[s] + (t + 1) * IN_ + lane);
        }

        // ---- tri-sample decoder pre-activations (shared weight regs) ----
        ull a[NS][4];
#pragma unroll
        for (int s = 0; s < NS; ++s) {
#pragma unroll
            for (int g = 0; g < 4; ++g) a[s][g] = dbp[g];
            fma2(a[s][0], dwih[0][0], hp0[s]); fma2(a[s][0], dwih[0][1], hp1[s]);
            fma2(a[s][1], dwih[1][0], hp0[s]); fma2(a[s][1], dwih[1][1], hp1[s]);
            fma2(a[s][2], dwih[2][0], hp0[s]); fma2(a[s][2], dwih[2][1], hp1[s]);
            fma2(a[s][3], dwih[3][0], hp0[s]); fma2(a[s][3], dwih[3][1], hp1[s]);
        }
        const int ph = t & 1;
#pragma unroll
        for (int m = 0; m < 7; ++m) {
#pragma unroll
            for (int s = 0; s < NS; ++s) {
                ulonglong2 v = ((const ulonglong2*)hbuf[w][s][ph])[m];
                fma2(a[s][0], dwhh[0][2*m], v.x); fma2(a[s][0], dwhh[0][2*m+1], v.y);
                fma2(a[s][1], dwhh[1][2*m], v.x); fma2(a[s][1], dwhh[1][2*m+1], v.y);
                fma2(a[s][2], dwhh[2][2*m], v.x); fma2(a[s][2], dwhh[2][2*m+1], v.y);
                fma2(a[s][3], dwhh[3][2*m], v.x); fma2(a[s][3], dwhh[3][2*m+1], v.y);
            }
        }

        // ---- encoders (skip on final iteration) ----
        if (t < T_) {
#pragma unroll
            for (int s = 0; s < NS; ++s)
                enc_step(ew, ebp, xoff, eA, eC, u, xbuf[w][s][ph],
                         he01[s], he23[s], ce[s]);
        }

        // ---- activations + stores ----
#pragma unroll
        for (int s = 0; s < NS; ++s) {
            float gi = sigm_pre(hadd2(a[s][0]));
            float gf = sigm_pre(hadd2(a[s][1]));
            float gg = tanh_a(hadd2(a[s][2]));
            float go = sigm_pre(hadd2(a[s][3]));
            float c  = gf * cd[s] + gi * gg;
            cd[s] = c;
            float h  = go * tanh_a(c);
            if (lane < HD_) {
                if (vs[s]) out[(size_t)bs[s] * T_ * HD_ + (t - 1) * HD_ + lane] = h;
                hbuf[w][s][(t - 1) & 1][lane] = h;
                if (t + 1 < T_) xbuf[w][s][(t + 1) & 1][lane] = xn[s];
            }
        }
        __syncwarp();
    }

    // ---------- classifier head + softmax per sample ----------
#pragma unroll
    for (int s = 0; s < NS; ++s) {
        ull hd[14];
        const ulonglong2* hv = (const ulonglong2*)hbuf[w][s][1];
#pragma unroll
        for (int m = 0; m < 7; ++m) { ulonglong2 v = hv[m]; hd[2*m] = v.x; hd[2*m+1] = v.y; }

        const int k = (lane < NC_) ? lane : (NC_ - 1);
        const ull* uwk = (const ull*)(sU + k * HD_);
        ull acc = pack2(sU[NC_ * HD_ + k], 0.f);
#pragma unroll
        for (int m = 0; m < 14; ++m) fma2(acc, uwk[m], hd[m]);
        float lg = hadd2(acc);

        float lv = (lane < NC_) ? lg : -3.4e38f;
#pragma unroll
        for (int o2 = 8; o2 >= 1; o2 >>= 1)
            lv = fmaxf(lv, __shfl_xor_sync(0xffffffffu, lv, o2, 16));
        float e = (lane < NC_) ? __expf(lg - lv) : 0.f;
        float sum = e;
#pragma unroll
        for (int o2 = 8; o2 >= 1; o2 >>= 1)
            sum += __shfl_xor_sync(0xffffffffu, sum, o2, 16);
        if (lane < NC_ && vs[s])
            pred[(size_t)bs[s] * NC_ + lane] = e * __fdividef(1.0f, sum);
    }
}

extern "C" void kernel_launch(void* const* d_in, const int* in_sizes, int n_in,
                              void* d_out, int out_size)
{
    const float* x    = (const float*)d_in[0];
    const float* eWih = (const float*)d_in[1];
    const float* eWhh = (const float*)d_in[2];
    const float* eb   = (const float*)d_in[3];
    const float* dWih = (const float*)d_in[4];
    const float* dWhh = (const float*)d_in[5];
    const float* db   = (const float*)d_in[6];
    const float* uW   = (const float*)d_in[7];
    const float* ub   = (const float*)d_in[8];

    float* out  = (float*)d_out;                 // [B, T, 28]
    float* pred = out + (size_t)B_ * T_ * HD_;   // [1, B, 10]

    const int spb = 4 * NS;                      // samples per block
    dim3 grid((B_ + spb - 1) / spb), block(128);
    ae_lstm_kernel<<<grid, block>>>(x, eWih, eWhh, eb, dWih, dWhh, db, uW, ub,
                                    out, pred);
}